// round 4
// baseline (speedup 1.0000x reference)
#include <cuda_runtime.h>

#define MAX_N 100000
#define MAX_E 1200000
#define FDIM 64
#define NB_MAX 128

// Scratch (device globals; no allocation allowed).
__device__ float g_Q[(size_t)MAX_N * FDIM];      // Q = X@W1 + (X*X)@W2
__device__ int   g_cnt[MAX_N];                   // per-row edge count (histogram)
__device__ int   g_rowstart[MAX_N];              // exclusive scan of g_cnt
__device__ int   g_cursor[MAX_N];                // scatter cursor (== row end after)
__device__ int2  g_edges[MAX_E];                 // binned (col, val) per row
__device__ int   g_bsum[NB_MAX];                 // per-build-block totals -> prefixes
__device__ int   g_bar;                          // spin-barrier counter (memset to 0)

// Barrier among the nb build blocks only (they are all wave-1 co-resident:
// build block ids < 148 <= first-wave capacity even at occupancy 1).
__device__ __forceinline__ void build_barrier(int target) {
    __syncthreads();
    if (threadIdx.x == 0) {
        __threadfence();
        atomicAdd(&g_bar, 1);
        while (*(volatile int*)&g_bar < target) { }
    }
    __syncthreads();
}

// ---------------------------------------------------------------------------
// Fused kernel.
//  blocks [0, nb)        : CSR build (hist -> scan -> scatter), self-synced.
//  blocks [nb, nb+denB)  : dense GEMM:
//       acc1 = X @ W1        -> out = acc1 + (b1+b2)
//       acc2 = (X*X) @ W2    -> Q   = acc1 + acc2
// The ~25us of build memory work hides under the FFMA-bound GEMM.
// ---------------------------------------------------------------------------
__global__ __launch_bounds__(256) void gnn_fused(
    const float* __restrict__ X,
    const float* __restrict__ W1, const float* __restrict__ b1,
    const float* __restrict__ W2, const float* __restrict__ b2,
    const int* __restrict__ rows,
    const int* __restrict__ cols,
    const float* __restrict__ vals,
    float* __restrict__ out, int N, int E, int nb)
{
    const int bid = blockIdx.x;
    const int tid = threadIdx.x;

    if (bid < nb) {
        // ================= BUILD ROLE =================
        const int lane = tid & 31, wid = tid >> 5;
        const int tstride = nb * 256;

        // Phase 0: histogram (g_cnt pre-zeroed by memset node)
        for (int e = bid * 256 + tid; e < E; e += tstride)
            atomicAdd(&g_cnt[__ldg(rows + e)], 1);
        build_barrier(nb);

        // Phase 1: per-block scan of 1024 counts (4 per thread)
        const int base = bid * 1024 + tid * 4;
        int c[4];
        #pragma unroll
        for (int u = 0; u < 4; ++u) {
            const int i = base + u;
            c[u] = (i < N) ? __ldcg(g_cnt + i) : 0;
        }
        const int s = c[0] + c[1] + c[2] + c[3];

        int incl = s;
        #pragma unroll
        for (int off = 1; off < 32; off <<= 1) {
            int u = __shfl_up_sync(0xffffffffu, incl, off);
            if (lane >= off) incl += u;
        }
        __shared__ int ws[8];
        if (lane == 31) ws[wid] = incl;
        __syncthreads();
        if (wid == 0 && lane < 8) {
            int x = ws[lane];
            #pragma unroll
            for (int off = 1; off < 8; off <<= 1) {
                int u = __shfl_up_sync(0xffu, x, off);
                if (lane >= off) x += u;
            }
            ws[lane] = x;
        }
        __syncthreads();
        const int texcl = incl - s + (wid ? ws[wid - 1] : 0);
        if (tid == 0) g_bsum[bid] = 0;          // placeholder-safe
        __syncthreads();
        if (tid == 255) g_bsum[bid] = texcl + s; // block total
        build_barrier(2 * nb);

        // Phase 2: serial exclusive scan of nb block totals (tiny)
        if (bid == 0 && tid == 0) {
            int acc = 0;
            for (int i = 0; i < nb; ++i) {
                const int t = __ldcg(g_bsum + i);
                g_bsum[i] = acc;
                acc += t;
            }
        }
        build_barrier(3 * nb);

        // Phase 3: write rowstart / cursor
        const int bbase = __ldcg(g_bsum + bid);
        int run = 0;
        #pragma unroll
        for (int u = 0; u < 4; ++u) {
            const int i = base + u;
            if (i < N) {
                const int ex = bbase + texcl + run;
                g_rowstart[i] = ex;
                g_cursor[i]   = ex;
            }
            run += c[u];
        }
        build_barrier(4 * nb);

        // Phase 4: scatter edges into row bins
        for (int e = bid * 256 + tid; e < E; e += tstride) {
            const int r   = __ldg(rows + e);
            const int pos = atomicAdd(&g_cursor[r], 1);
            g_edges[pos] = make_int2(__ldg(cols + e),
                                     __float_as_int(__ldg(vals + e)));
        }
        return;
    }

    // ================= DENSE GEMM ROLE =================
    extern __shared__ float smem[];
    float* W1s = smem;          // 64*64
    float* W2s = smem + 4096;   // 64*64
    float* Xs  = smem + 8192;   // 128*64

    #pragma unroll
    for (int i = tid; i < 1024; i += 256) {
        reinterpret_cast<float4*>(W1s)[i] = reinterpret_cast<const float4*>(W1)[i];
        reinterpret_cast<float4*>(W2s)[i] = reinterpret_cast<const float4*>(W2)[i];
    }

    const int row0 = (bid - nb) * 128;
    #pragma unroll
    for (int i = tid; i < 128 * 16; i += 256) {
        const int r  = i >> 4;
        const int gr = row0 + r;
        float4 v = make_float4(0.f, 0.f, 0.f, 0.f);
        if (gr < N) v = reinterpret_cast<const float4*>(X)[(size_t)gr * 16 + (i & 15)];
        reinterpret_cast<float4*>(Xs)[i] = v;
    }
    __syncthreads();

    const int rg  = (tid >> 4) * 8;
    const int cg4 = tid & 15;

    float acc1[8][4];
    float acc2[8][4];
    #pragma unroll
    for (int i = 0; i < 8; ++i)
        #pragma unroll
        for (int j = 0; j < 4; ++j) { acc1[i][j] = 0.f; acc2[i][j] = 0.f; }

    #pragma unroll 4
    for (int k = 0; k < 64; ++k) {
        const float4 w1 = reinterpret_cast<const float4*>(W1s + k * 64)[cg4];
        const float4 w2 = reinterpret_cast<const float4*>(W2s + k * 64)[cg4];
        #pragma unroll
        for (int i = 0; i < 8; ++i) {
            const float x  = Xs[(rg + i) * 64 + k];
            const float x2 = x * x;
            acc1[i][0] = fmaf(x,  w1.x, acc1[i][0]);
            acc1[i][1] = fmaf(x,  w1.y, acc1[i][1]);
            acc1[i][2] = fmaf(x,  w1.z, acc1[i][2]);
            acc1[i][3] = fmaf(x,  w1.w, acc1[i][3]);
            acc2[i][0] = fmaf(x2, w2.x, acc2[i][0]);
            acc2[i][1] = fmaf(x2, w2.y, acc2[i][1]);
            acc2[i][2] = fmaf(x2, w2.z, acc2[i][2]);
            acc2[i][3] = fmaf(x2, w2.w, acc2[i][3]);
        }
    }

    const int cc = cg4 * 4;
    float4 bb;
    bb.x = __ldg(b1 + cc + 0) + __ldg(b2 + cc + 0);
    bb.y = __ldg(b1 + cc + 1) + __ldg(b2 + cc + 1);
    bb.z = __ldg(b1 + cc + 2) + __ldg(b2 + cc + 2);
    bb.w = __ldg(b1 + cc + 3) + __ldg(b2 + cc + 3);

    #pragma unroll
    for (int i = 0; i < 8; ++i) {
        const int gr = row0 + rg + i;
        if (gr < N) {
            float4 o, q;
            o.x = acc1[i][0] + bb.x;  q.x = acc1[i][0] + acc2[i][0];
            o.y = acc1[i][1] + bb.y;  q.y = acc1[i][1] + acc2[i][1];
            o.z = acc1[i][2] + bb.z;  q.z = acc1[i][2] + acc2[i][2];
            o.w = acc1[i][3] + bb.w;  q.w = acc1[i][3] + acc2[i][3];
            reinterpret_cast<float4*>(out)[(size_t)gr * 16 + cg4] = o;
            reinterpret_cast<float4*>(g_Q)[(size_t)gr * 16 + cg4] = q;
        }
    }
}

// ---------------------------------------------------------------------------
// CSR SpMM: one warp per row, register accumulation, no float atomics.
// out[r] += sum_j val_j * Q[col_j]   (out already holds the dense part)
// ---------------------------------------------------------------------------
__global__ __launch_bounds__(256) void gnn_spmm_csr(float* __restrict__ out, int N)
{
    const int warp = (blockIdx.x * blockDim.x + threadIdx.x) >> 5;
    if (warp >= N) return;
    const int lane = threadIdx.x & 31;

    const int start = __ldg(g_rowstart + warp);
    const int end   = __ldg(g_cursor + warp);
    if (end <= start) return;

    const float2* __restrict__ Q2 = reinterpret_cast<const float2*>(g_Q);
    float2 acc = make_float2(0.f, 0.f);

    int j = start;
    // 4-way unrolled: four independent gather chains in flight.
    for (; j + 3 < end; j += 4) {
        const int2 cv0 = __ldg(g_edges + j);
        const int2 cv1 = __ldg(g_edges + j + 1);
        const int2 cv2 = __ldg(g_edges + j + 2);
        const int2 cv3 = __ldg(g_edges + j + 3);
        const float2 q0 = __ldg(Q2 + (size_t)cv0.x * 32 + lane);
        const float2 q1 = __ldg(Q2 + (size_t)cv1.x * 32 + lane);
        const float2 q2 = __ldg(Q2 + (size_t)cv2.x * 32 + lane);
        const float2 q3 = __ldg(Q2 + (size_t)cv3.x * 32 + lane);
        acc.x = fmaf(__int_as_float(cv0.y), q0.x, acc.x);
        acc.y = fmaf(__int_as_float(cv0.y), q0.y, acc.y);
        acc.x = fmaf(__int_as_float(cv1.y), q1.x, acc.x);
        acc.y = fmaf(__int_as_float(cv1.y), q1.y, acc.y);
        acc.x = fmaf(__int_as_float(cv2.y), q2.x, acc.x);
        acc.y = fmaf(__int_as_float(cv2.y), q2.y, acc.y);
        acc.x = fmaf(__int_as_float(cv3.y), q3.x, acc.x);
        acc.y = fmaf(__int_as_float(cv3.y), q3.y, acc.y);
    }
    for (; j < end; ++j) {
        const int2 cv = __ldg(g_edges + j);
        const float2 q = __ldg(Q2 + (size_t)cv.x * 32 + lane);
        acc.x = fmaf(__int_as_float(cv.y), q.x, acc.x);
        acc.y = fmaf(__int_as_float(cv.y), q.y, acc.y);
    }

    float2* orow = reinterpret_cast<float2*>(out) + (size_t)warp * 32 + lane;
    float2 o = *orow;
    o.x += acc.x;
    o.y += acc.y;
    *orow = o;
}

extern "C" void kernel_launch(void* const* d_in, const int* in_sizes, int n_in,
                              void* d_out, int out_size)
{
    const int*   rows = (const int*)  d_in[0];
    const int*   cols = (const int*)  d_in[1];
    const float* vals = (const float*)d_in[2];
    const float* X    = (const float*)d_in[3];
    const float* W1   = (const float*)d_in[4];
    const float* b1   = (const float*)d_in[5];
    const float* W2   = (const float*)d_in[6];
    const float* b2   = (const float*)d_in[7];
    float* out = (float*)d_out;

    const int E = in_sizes[0];
    const int N = in_sizes[3] / FDIM;
    const int nb = (N + 1023) / 1024;           // 98 build blocks (< 148)

    cudaFuncSetAttribute(gnn_fused, cudaFuncAttributeMaxDynamicSharedMemorySize, 65536);

    // Reset histogram + barrier counter (capture-safe memset nodes).
    void* p = nullptr;
    cudaGetSymbolAddress(&p, g_cnt);
    cudaMemsetAsync(p, 0, (size_t)N * sizeof(int));
    cudaGetSymbolAddress(&p, g_bar);
    cudaMemsetAsync(p, 0, sizeof(int));

    const int denB = (N + 127) / 128;
    gnn_fused<<<nb + denB, 256, 65536>>>(X, W1, b1, W2, b2,
                                         rows, cols, vals, out, N, E, nb);

    const long long work = (long long)N * 32;
    gnn_spmm_csr<<<(int)((work + 255) / 256), 256>>>(out, N);
}